// round 11
// baseline (speedup 1.0000x reference)
#include <cuda_runtime.h>
#include <math_constants.h>

#define MAXQ    4096
#define MAXM    100000
#define MARGIN  0.0625f

// Grid over [-5,5]^3, cell 0.25. Clamped binning is 1-Lipschitz, so any mean
// within distance 0.25 of a query lies in the query cell's 27-neighborhood.
// Exact for arbitrary inputs (border cells treated as extending to infinity
// for the pruning bound).
#define GS      40
#define NC      (GS * GS * GS)          // 64000
#define SCANBLK 63
#define NCPAD   (SCANBLK * 1024)        // 64512 (padded cells always zero)

#define FP_SCALE 17179869184.0          // 2^34

// ---- static device scratch (zero-init at load; invariants restored each run) ----
__device__ float4             g_q[MAXQ];
__device__ int                g_cnt[NCPAD];     // re-zeroed by scan_scatter_kernel
__device__ int                g_off[NCPAD + 1];
__device__ int                g_fill[NCPAD];
__device__ float4             g_pts[MAXM];
__device__ int                g_bsum[SCANBLK];
__device__ unsigned int       g_barcnt;         // cumulative grid-barrier counter
__device__ unsigned int       g_sdone;          // scatter ticket
__device__ unsigned long long g_acc;            // fixed-point loss accumulator
__device__ unsigned int       g_done;           // query ticket

__device__ __forceinline__ int cell1d(float v) {
    int c = (int)floorf((v + 5.0f) * 4.0f);
    return min(max(c, 0), GS - 1);
}

// Per-axis distance from v to cell i's effective region (clamp-extended at borders)
__device__ __forceinline__ float axd(float v, int i) {
    float lo = fmaf(0.25f, (float)i, -5.0f);
    float hi = lo + 0.25f;
    float d = 0.f;
    if (i > 0 && v < lo)           d = lo - v;
    else if (i < GS - 1 && v > hi) d = v - hi;
    return d;
}

// Grid barrier among co-resident blocks (cumulative target, no reset here)
__device__ __forceinline__ void gbar(unsigned target) {
    __syncthreads();
    if (threadIdx.x == 0) {
        __threadfence();
        atomicAdd(&g_barcnt, 1u);
        while (atomicAdd(&g_barcnt, 0u) < target) {}
        __threadfence();
    }
    __syncthreads();
}

// ---------------------------------------------------------------------------
// Kernel 1: transform queries + count means per cell (g_cnt zero on entry)
// ---------------------------------------------------------------------------
__global__ void prep_count_kernel(const float* __restrict__ outputs,
                                  const float* __restrict__ c2ws,
                                  const float* __restrict__ scales,
                                  const float* __restrict__ means,
                                  int N, int Qtot, int M) {
    int gid = blockIdx.x * blockDim.x + threadIdx.x;

    if (gid < Qtot) {
        int b = gid / N, n = gid % N;
        float s = scales[b];
        const float* o = outputs + ((size_t)b * N + n) * 3;
        const float* c = c2ws + (size_t)b * 16;
        float ox = o[0], oy = o[1], oz = o[2];
        float qx = fmaf(s, fmaf(ox, c[0], fmaf(oy, c[1], oz * c[2])),  c[3]);
        float qy = fmaf(s, fmaf(ox, c[4], fmaf(oy, c[5], oz * c[6])),  c[7]);
        float qz = fmaf(s, fmaf(ox, c[8], fmaf(oy, c[9], oz * c[10])), c[11]);
        g_q[gid] = make_float4(qx, qy, qz, 0.f);
    }

    if (gid < M) {
        int cx = cell1d(means[3 * gid + 0]);
        int cy = cell1d(means[3 * gid + 1]);
        int cz = cell1d(means[3 * gid + 2]);
        atomicAdd(&g_cnt[(cz * GS + cy) * GS + cx], 1);
    }
}

// ---------------------------------------------------------------------------
// Kernel 2: fused exclusive scan + scatter. 63 blocks (all co-resident on 148
// SMs) with 2 internal grid barriers. Re-zeroes g_cnt; last scatter ticket
// resets barrier + ticket counters for the next graph replay.
// ---------------------------------------------------------------------------
__global__ void __launch_bounds__(256) scan_scatter_kernel(
        const float* __restrict__ means, int M) {
    __shared__ int ws_incl[8];
    __shared__ int ws_excl[8];
    __shared__ int sh_prefix;

    const int tid  = threadIdx.x;
    const int bid  = blockIdx.x;
    const int lane = tid & 31;
    const int w    = tid >> 5;
    const int base = bid * 1024 + tid * 4;

    int4 v = *(const int4*)&g_cnt[base];
    int s = v.x + v.y + v.z + v.w;

    int inc = s;
#pragma unroll
    for (int o = 1; o < 32; o <<= 1) {
        int t = __shfl_up_sync(0xFFFFFFFFu, inc, o);
        if (lane >= o) inc += t;
    }
    if (lane == 31) ws_incl[w] = inc;
    __syncthreads();
    if (tid < 8) {
        int e = 0;
#pragma unroll
        for (int k = 0; k < 8; ++k)
            if (k < tid) e += ws_incl[k];
        ws_excl[tid] = e;
    }
    __syncthreads();

    const int block_total = ws_excl[7] + ws_incl[7];
    const int excl = (inc - s) + ws_excl[w];

    if (tid == 0) g_bsum[bid] = block_total;

    gbar(SCANBLK);                       // all block totals visible

    if (tid == 0) {
        int p = 0;
        for (int i = 0; i < bid; ++i) p += g_bsum[i];
        sh_prefix = p;
    }
    __syncthreads();

    const int p = sh_prefix + excl;
    g_off[base + 0]  = p;
    g_off[base + 1]  = p + v.x;
    g_off[base + 2]  = p + v.x + v.y;
    g_off[base + 3]  = p + v.x + v.y + v.z;
    g_fill[base + 0] = p;
    g_fill[base + 1] = p + v.x;
    g_fill[base + 2] = p + v.x + v.y;
    g_fill[base + 3] = p + v.x + v.y + v.z;
    *(int4*)&g_cnt[base] = make_int4(0, 0, 0, 0);   // restore zero-invariant
    if (bid == SCANBLK - 1 && tid == 255)
        g_off[NCPAD] = p + v.x + v.y + v.z + v.w;

    gbar(2 * SCANBLK);                   // all offsets + cursors visible

    // scatter (grid-stride over means)
    for (int m = bid * 256 + tid; m < M; m += SCANBLK * 256) {
        float x = means[3 * m + 0];
        float y = means[3 * m + 1];
        float z = means[3 * m + 2];
        int c = (cell1d(z) * GS + cell1d(y)) * GS + cell1d(x);
        int pos = atomicAdd(&g_fill[c], 1);
        g_pts[pos] = make_float4(x, y, z, 0.f);
    }

    // reset barrier/ticket state (safe: resetter is the last block to finish,
    // and no block reads g_barcnt after passing the final barrier)
    __syncthreads();
    if (tid == 0) {
        __threadfence();
        if (atomicAdd(&g_sdone, 1u) == SCANBLK - 1) {
            atomicExch(&g_barcnt, 0u);
            atomicExch(&g_sdone, 0u);
        }
    }
}

// ---------------------------------------------------------------------------
// Kernel 3: warp-per-query NN with exact cell pruning + fused deterministic
// reduction (u64 fixed-point atomicAdd; last ticket writes out & resets).
//   - best starts at MARGIN: mins above MARGIN contribute 0 to the hinge.
//   - home cell scanned first; neighbor cell visited only if box-dist^2 < best
//     (box = clamp-extended cell region -> exact lower bound for any inputs).
// ---------------------------------------------------------------------------
__global__ void __launch_bounds__(256) query_kernel(float* __restrict__ out, int Q) {
    __shared__ float wterm[8];
    const int tid  = threadIdx.x;
    const int lane = tid & 31;
    const int warp = tid >> 5;
    const int qid  = blockIdx.x * 8 + warp;

    float term = 0.f;
    if (qid < Q) {
        float4 qv = g_q[qid];
        const int cx = cell1d(qv.x), cy = cell1d(qv.y), cz = cell1d(qv.z);
        float best = MARGIN;

        // home cell first (box-dist 0)
        {
            const int home = (cz * GS + cy) * GS + cx;
            const int s0 = g_off[home], e0 = g_off[home + 1];
            float lb = best;
            for (int t = s0 + lane; t < e0; t += 32) {
                float4 m = g_pts[t];
                float dx = qv.x - m.x, dy = qv.y - m.y, dz = qv.z - m.z;
                lb = fminf(lb, fmaf(dx, dx, fmaf(dy, dy, dz * dz)));
            }
#pragma unroll
            for (int o = 16; o; o >>= 1)
                lb = fminf(lb, __shfl_xor_sync(0xFFFFFFFFu, lb, o));
            best = lb;
        }

        const int x0 = max(cx - 1, 0), x1 = min(cx + 1, GS - 1);
        const int y0 = max(cy - 1, 0), y1 = min(cy + 1, GS - 1);
        const int z0 = max(cz - 1, 0), z1 = min(cz + 1, GS - 1);

        for (int zi = z0; zi <= z1; ++zi) {
            const float az = axd(qv.z, zi);
            const float az2 = az * az;
            if (az2 >= best) continue;
            for (int yi = y0; yi <= y1; ++yi) {
                const float ay = axd(qv.y, yi);
                const float byz = fmaf(ay, ay, az2);
                if (byz >= best) continue;
                const int row = (zi * GS + yi) * GS;
                for (int xi = x0; xi <= x1; ++xi) {
                    if (xi == cx && yi == cy && zi == cz) continue;
                    const float ax = axd(qv.x, xi);
                    const float bd = fmaf(ax, ax, byz);
                    if (bd >= best) continue;
                    const int c = row + xi;
                    const int s0 = g_off[c], e0 = g_off[c + 1];
                    float lb = best;
                    for (int t = s0 + lane; t < e0; t += 32) {
                        float4 m = g_pts[t];
                        float dx = qv.x - m.x, dy = qv.y - m.y, dz = qv.z - m.z;
                        lb = fminf(lb, fmaf(dx, dx, fmaf(dy, dy, dz * dz)));
                    }
#pragma unroll
                    for (int o = 16; o; o >>= 1)
                        lb = fminf(lb, __shfl_xor_sync(0xFFFFFFFFu, lb, o));
                    best = fminf(best, lb);
                }
            }
        }
        term = MARGIN - best;            // best in [0, MARGIN] -> term in [0, MARGIN]
    }

    if (lane == 0) wterm[warp] = term;
    __syncthreads();

    if (tid == 0) {
        double s = 0.0;
#pragma unroll
        for (int w = 0; w < 8; ++w) s += (double)wterm[w];
        unsigned long long fx = (unsigned long long)__double2ll_rn(s * FP_SCALE);
        atomicAdd(&g_acc, fx);
        __threadfence();
        if (atomicAdd(&g_done, 1u) == gridDim.x - 1) {
            unsigned long long tot = atomicExch(&g_acc, 0ull);
            atomicExch(&g_done, 0u);
            out[0] = (float)(((double)tot / FP_SCALE) / (double)Q);
        }
    }
}

extern "C" void kernel_launch(void* const* d_in, const int* in_sizes, int n_in,
                              void* d_out, int out_size) {
    const float* outputs = (const float*)d_in[0];  // (B, N, 3)
    const float* c2ws    = (const float*)d_in[1];  // (B, 4, 4)
    const float* scales  = (const float*)d_in[2];  // (B,)
    const float* means   = (const float*)d_in[3];  // (M, 3)

    int B = in_sizes[2];
    int Q = in_sizes[0] / 3;              // B*N
    int N = (B > 0) ? (Q / B) : 0;
    int M = in_sizes[3] / 3;
    if (Q > MAXQ) Q = MAXQ;
    if (M > MAXM) M = MAXM;

    int work = M > Q ? M : Q;
    int nb1  = (work + 255) / 256;
    int nqb  = (Q + 7) / 8;

    prep_count_kernel  <<<nb1, 256>>>(outputs, c2ws, scales, means, N, Q, M);
    scan_scatter_kernel<<<SCANBLK, 256>>>(means, M);
    query_kernel       <<<nqb, 256>>>((float*)d_out, Q);
}

// round 12
// speedup vs baseline: 1.0439x; 1.0439x over previous
#include <cuda_runtime.h>
#include <math_constants.h>

#define MAXQ    4096
#define MAXM    100000
#define MARGIN  0.0625f

// Grid over [-4,4]^3, cell 0.25. Clamped binning is 1-Lipschitz, so any mean
// within distance 0.25 of a query lies in the query cell's 27-neighborhood.
// Exact for arbitrary inputs (border cells clamp-extended to infinity in the
// pruning bound).
#define GS      32
#define NC      (GS * GS * GS)     // 32768 = 32 * 1024
#define SCANBLK 32

#define FP_SCALE 17179869184.0     // 2^34

// ---- static device scratch (zero-init at load; invariants restored each run) ----
__device__ float4             g_q[MAXQ];
__device__ int                g_cnt[NC];        // re-zeroed by scan_kernel
__device__ int                g_off[NC + 1];
__device__ int                g_fill[NC];
__device__ float4             g_pts[MAXM];
__device__ unsigned long long g_state[SCANBLK]; // lookback: flag<<62 | value
__device__ unsigned long long g_acc;            // fixed-point loss accumulator
__device__ unsigned int       g_done;           // query ticket

__device__ __forceinline__ int cell1d(float v) {
    int c = (int)floorf((v + 4.0f) * 4.0f);
    return min(max(c, 0), GS - 1);
}
__device__ __forceinline__ int cidx(float x, float y, float z) {
    return (cell1d(z) * GS + cell1d(y)) * GS + cell1d(x);
}

// Per-axis distance from v to cell i's effective region (clamp-extended at borders)
__device__ __forceinline__ float axd(float v, int i) {
    float lo = fmaf(0.25f, (float)i, -4.0f);
    float hi = lo + 0.25f;
    float d = 0.f;
    if (i > 0 && v < lo)           d = lo - v;
    else if (i < GS - 1 && v > hi) d = v - hi;
    return d;
}

// ---------------------------------------------------------------------------
// Kernel 1: reset lookback state + transform queries + count means per cell.
// Means processed 4-per-thread via float4 loads (MLP + fewer threads).
// ---------------------------------------------------------------------------
__global__ void prep_count_kernel(const float* __restrict__ outputs,
                                  const float* __restrict__ c2ws,
                                  const float* __restrict__ scales,
                                  const float* __restrict__ means,
                                  int N, int Qtot, int M) {
    int gid = blockIdx.x * blockDim.x + threadIdx.x;

    if (gid < SCANBLK) g_state[gid] = 0ull;

    if (gid < Qtot) {
        int b = gid / N, n = gid % N;
        float s = scales[b];
        const float* o = outputs + ((size_t)b * N + n) * 3;
        const float* c = c2ws + (size_t)b * 16;
        float ox = o[0], oy = o[1], oz = o[2];
        float qx = fmaf(s, fmaf(ox, c[0], fmaf(oy, c[1], oz * c[2])),  c[3]);
        float qy = fmaf(s, fmaf(ox, c[4], fmaf(oy, c[5], oz * c[6])),  c[7]);
        float qz = fmaf(s, fmaf(ox, c[8], fmaf(oy, c[9], oz * c[10])), c[11]);
        g_q[gid] = make_float4(qx, qy, qz, 0.f);
    }

    int m0 = gid * 4;
    if (m0 + 4 <= M) {
        const float4* p = (const float4*)means + (size_t)gid * 3;
        float4 a = p[0], b = p[1], c = p[2];
        atomicAdd(&g_cnt[cidx(a.x, a.y, a.z)], 1);
        atomicAdd(&g_cnt[cidx(a.w, b.x, b.y)], 1);
        atomicAdd(&g_cnt[cidx(b.z, b.w, c.x)], 1);
        atomicAdd(&g_cnt[cidx(c.y, c.z, c.w)], 1);
    } else if (m0 < M) {
        for (int m = m0; m < M; ++m)
            atomicAdd(&g_cnt[cidx(means[3*m], means[3*m+1], means[3*m+2])], 1);
    }
}

// ---------------------------------------------------------------------------
// Kernel 2: single-kernel ordered exclusive scan (decoupled lookback).
// 32 blocks x 256 threads, 4 cells/thread. All co-resident -> no deadlock.
// Zeroes g_cnt behind itself (restores invariant for next graph replay).
// ---------------------------------------------------------------------------
__global__ void __launch_bounds__(256) scan_kernel() {
    __shared__ int ws_incl[8];
    __shared__ int ws_excl[8];
    __shared__ int sh_prefix;

    const int tid  = threadIdx.x;
    const int bid  = blockIdx.x;
    const int lane = tid & 31;
    const int w    = tid >> 5;
    const int base = bid * 1024 + tid * 4;

    int4 v = *(const int4*)&g_cnt[base];
    int s = v.x + v.y + v.z + v.w;

    int inc = s;
#pragma unroll
    for (int o = 1; o < 32; o <<= 1) {
        int t = __shfl_up_sync(0xFFFFFFFFu, inc, o);
        if (lane >= o) inc += t;
    }
    if (lane == 31) ws_incl[w] = inc;
    __syncthreads();
    if (tid < 8) {
        int e = 0;
#pragma unroll
        for (int k = 0; k < 8; ++k)
            if (k < tid) e += ws_incl[k];
        ws_excl[tid] = e;
    }
    __syncthreads();

    const int block_total = ws_excl[7] + ws_incl[7];
    const int excl = (inc - s) + ws_excl[w];

    if (tid == 0) {
        atomicExch(&g_state[bid], (1ull << 62) | (unsigned long long)block_total);
        unsigned long long prefix = 0;
        for (int i = bid - 1; i >= 0;) {
            unsigned long long st;
            do { st = atomicAdd(&g_state[i], 0ull); } while ((st >> 62) == 0ull);
            prefix += st & 0x3FFFFFFFFFFFFFFFull;
            if ((st >> 62) == 2ull) break;
            --i;
        }
        atomicExch(&g_state[bid],
                   (2ull << 62) | (unsigned long long)(prefix + block_total));
        sh_prefix = (int)prefix;
    }
    __syncthreads();

    const int p = sh_prefix + excl;
    int4 ov = make_int4(p, p + v.x, p + v.x + v.y, p + v.x + v.y + v.z);
    *(int4*)&g_off[base]  = ov;
    *(int4*)&g_fill[base] = ov;
    *(int4*)&g_cnt[base]  = make_int4(0, 0, 0, 0);   // restore zero-invariant

    if (bid == SCANBLK - 1 && tid == 255)
        g_off[NC] = ov.w + v.w;
}

// ---------------------------------------------------------------------------
// Kernel 3: scatter means into cell-sorted order (4 means/thread, float4 loads)
// ---------------------------------------------------------------------------
__global__ void scatter_kernel(const float* __restrict__ means, int M) {
    int gid = blockIdx.x * blockDim.x + threadIdx.x;
    int m0 = gid * 4;
    if (m0 + 4 <= M) {
        const float4* p = (const float4*)means + (size_t)gid * 3;
        float4 a = p[0], b = p[1], c = p[2];
        int p0 = atomicAdd(&g_fill[cidx(a.x, a.y, a.z)], 1);
        g_pts[p0] = make_float4(a.x, a.y, a.z, 0.f);
        int p1 = atomicAdd(&g_fill[cidx(a.w, b.x, b.y)], 1);
        g_pts[p1] = make_float4(a.w, b.x, b.y, 0.f);
        int p2 = atomicAdd(&g_fill[cidx(b.z, b.w, c.x)], 1);
        g_pts[p2] = make_float4(b.z, b.w, c.x, 0.f);
        int p3 = atomicAdd(&g_fill[cidx(c.y, c.z, c.w)], 1);
        g_pts[p3] = make_float4(c.y, c.z, c.w, 0.f);
    } else if (m0 < M) {
        for (int m = m0; m < M; ++m) {
            float x = means[3*m], y = means[3*m+1], z = means[3*m+2];
            int pos = atomicAdd(&g_fill[cidx(x, y, z)], 1);
            g_pts[pos] = make_float4(x, y, z, 0.f);
        }
    }
}

// ---------------------------------------------------------------------------
// Kernel 4: warp-per-query NN with exact cell pruning + fused deterministic
// reduction (u64 fixed-point atomicAdd; last ticket writes out & resets).
//   - best starts at MARGIN: mins above MARGIN contribute 0 to the hinge.
//   - home cell first; neighbor visited only if clamp-extended box-dist^2 < best.
// ---------------------------------------------------------------------------
__global__ void __launch_bounds__(256) query_kernel(float* __restrict__ out, int Q) {
    __shared__ float wterm[8];
    const int tid  = threadIdx.x;
    const int lane = tid & 31;
    const int warp = tid >> 5;
    const int qid  = blockIdx.x * 8 + warp;

    float term = 0.f;
    if (qid < Q) {
        float4 qv = g_q[qid];
        const int cx = cell1d(qv.x), cy = cell1d(qv.y), cz = cell1d(qv.z);
        float best = MARGIN;

        // home cell first (box-dist 0)
        {
            const int home = (cz * GS + cy) * GS + cx;
            const int s0 = g_off[home], e0 = g_off[home + 1];
            float lb = best;
            for (int t = s0 + lane; t < e0; t += 32) {
                float4 m = g_pts[t];
                float dx = qv.x - m.x, dy = qv.y - m.y, dz = qv.z - m.z;
                lb = fminf(lb, fmaf(dx, dx, fmaf(dy, dy, dz * dz)));
            }
#pragma unroll
            for (int o = 16; o; o >>= 1)
                lb = fminf(lb, __shfl_xor_sync(0xFFFFFFFFu, lb, o));
            best = lb;
        }

        const int x0 = max(cx - 1, 0), x1 = min(cx + 1, GS - 1);
        const int y0 = max(cy - 1, 0), y1 = min(cy + 1, GS - 1);
        const int z0 = max(cz - 1, 0), z1 = min(cz + 1, GS - 1);

        for (int zi = z0; zi <= z1; ++zi) {
            const float az = axd(qv.z, zi);
            const float az2 = az * az;
            if (az2 >= best) continue;
            for (int yi = y0; yi <= y1; ++yi) {
                const float ay = axd(qv.y, yi);
                const float byz = fmaf(ay, ay, az2);
                if (byz >= best) continue;
                const int row = (zi * GS + yi) * GS;
                for (int xi = x0; xi <= x1; ++xi) {
                    if (xi == cx && yi == cy && zi == cz) continue;
                    const float ax = axd(qv.x, xi);
                    const float bd = fmaf(ax, ax, byz);
                    if (bd >= best) continue;
                    const int c = row + xi;
                    const int s0 = g_off[c], e0 = g_off[c + 1];
                    float lb = best;
                    for (int t = s0 + lane; t < e0; t += 32) {
                        float4 m = g_pts[t];
                        float dx = qv.x - m.x, dy = qv.y - m.y, dz = qv.z - m.z;
                        lb = fminf(lb, fmaf(dx, dx, fmaf(dy, dy, dz * dz)));
                    }
#pragma unroll
                    for (int o = 16; o; o >>= 1)
                        lb = fminf(lb, __shfl_xor_sync(0xFFFFFFFFu, lb, o));
                    best = fminf(best, lb);
                }
            }
        }
        term = MARGIN - best;            // best in [0, MARGIN]
    }

    if (lane == 0) wterm[warp] = term;
    __syncthreads();

    if (tid == 0) {
        double s = 0.0;
#pragma unroll
        for (int w = 0; w < 8; ++w) s += (double)wterm[w];
        unsigned long long fx = (unsigned long long)__double2ll_rn(s * FP_SCALE);
        atomicAdd(&g_acc, fx);
        __threadfence();
        if (atomicAdd(&g_done, 1u) == gridDim.x - 1) {
            unsigned long long tot = atomicExch(&g_acc, 0ull);
            atomicExch(&g_done, 0u);
            out[0] = (float)(((double)tot / FP_SCALE) / (double)Q);
        }
    }
}

extern "C" void kernel_launch(void* const* d_in, const int* in_sizes, int n_in,
                              void* d_out, int out_size) {
    const float* outputs = (const float*)d_in[0];  // (B, N, 3)
    const float* c2ws    = (const float*)d_in[1];  // (B, 4, 4)
    const float* scales  = (const float*)d_in[2];  // (B,)
    const float* means   = (const float*)d_in[3];  // (M, 3)

    int B = in_sizes[2];
    int Q = in_sizes[0] / 3;              // B*N
    int N = (B > 0) ? (Q / B) : 0;
    int M = in_sizes[3] / 3;
    if (Q > MAXQ) Q = MAXQ;
    if (M > MAXM) M = MAXM;

    int mthreads = (M + 3) / 4;           // 4 means per thread
    int work = mthreads > Q ? mthreads : Q;
    int nb1  = (work + 255) / 256;
    int nbs  = (mthreads + 255) / 256;
    int nqb  = (Q + 7) / 8;

    prep_count_kernel<<<nb1, 256>>>(outputs, c2ws, scales, means, N, Q, M);
    scan_kernel      <<<SCANBLK, 256>>>();
    scatter_kernel   <<<nbs, 256>>>(means, M);
    query_kernel     <<<nqb, 256>>>((float*)d_out, Q);
}

// round 13
// speedup vs baseline: 1.1210x; 1.0738x over previous
#include <cuda_runtime.h>
#include <math_constants.h>

#define MAXQ    4096
#define MAXM    100000
#define MARGIN  0.0625f

// Grid over [-4,4]^3, cell 0.25. Clamped binning is 1-Lipschitz, so any mean
// within distance 0.25 of a query lies in the query cell's 27-neighborhood.
// Exact for arbitrary inputs (border cells clamp-extended to infinity in the
// pruning bound).
#define GS      32
#define NC      (GS * GS * GS)     // 32768 = 32 * 1024
#define SCANBLK 32

#define FP_SCALE 17179869184.0     // 2^34

// ---- static device scratch (zero-init at load; invariants restored each run) ----
__device__ float4             g_q[MAXQ];
__device__ int                g_cnt[NC];        // re-zeroed by scan_kernel
__device__ int                g_off[NC + 1];
__device__ int                g_fill[NC];
__device__ float4             g_pts[MAXM];
__device__ unsigned long long g_state[SCANBLK]; // lookback: flag<<62 | value
__device__ unsigned long long g_acc;            // fixed-point loss accumulator
__device__ unsigned int       g_done;           // query ticket

__device__ __forceinline__ int cell1d(float v) {
    int c = (int)floorf((v + 4.0f) * 4.0f);
    return min(max(c, 0), GS - 1);
}
__device__ __forceinline__ int cidx(float x, float y, float z) {
    return (cell1d(z) * GS + cell1d(y)) * GS + cell1d(x);
}

// Per-axis distance from v to cell i's effective region (clamp-extended at borders)
__device__ __forceinline__ float axd(float v, int i) {
    float lo = fmaf(0.25f, (float)i, -4.0f);
    float hi = lo + 0.25f;
    float d = 0.f;
    if (i > 0 && v < lo)           d = lo - v;
    else if (i < GS - 1 && v > hi) d = v - hi;
    return d;
}

// ---------------------------------------------------------------------------
// Kernel 1: reset lookback state + transform queries + count means per cell.
// Means processed 4-per-thread via float4 loads (MLP + fewer threads).
// ---------------------------------------------------------------------------
__global__ void prep_count_kernel(const float* __restrict__ outputs,
                                  const float* __restrict__ c2ws,
                                  const float* __restrict__ scales,
                                  const float* __restrict__ means,
                                  int N, int Qtot, int M) {
    int gid = blockIdx.x * blockDim.x + threadIdx.x;

    if (gid < SCANBLK) g_state[gid] = 0ull;

    if (gid < Qtot) {
        int b = gid / N, n = gid % N;
        float s = scales[b];
        const float* o = outputs + ((size_t)b * N + n) * 3;
        const float* c = c2ws + (size_t)b * 16;
        float ox = o[0], oy = o[1], oz = o[2];
        float qx = fmaf(s, fmaf(ox, c[0], fmaf(oy, c[1], oz * c[2])),  c[3]);
        float qy = fmaf(s, fmaf(ox, c[4], fmaf(oy, c[5], oz * c[6])),  c[7]);
        float qz = fmaf(s, fmaf(ox, c[8], fmaf(oy, c[9], oz * c[10])), c[11]);
        g_q[gid] = make_float4(qx, qy, qz, 0.f);
    }

    int m0 = gid * 4;
    if (m0 + 4 <= M) {
        const float4* p = (const float4*)means + (size_t)gid * 3;
        float4 a = p[0], b = p[1], c = p[2];
        atomicAdd(&g_cnt[cidx(a.x, a.y, a.z)], 1);
        atomicAdd(&g_cnt[cidx(a.w, b.x, b.y)], 1);
        atomicAdd(&g_cnt[cidx(b.z, b.w, c.x)], 1);
        atomicAdd(&g_cnt[cidx(c.y, c.z, c.w)], 1);
    } else if (m0 < M) {
        for (int m = m0; m < M; ++m)
            atomicAdd(&g_cnt[cidx(means[3*m], means[3*m+1], means[3*m+2])], 1);
    }
}

// ---------------------------------------------------------------------------
// Kernel 2: single-kernel ordered exclusive scan (decoupled lookback).
// 32 blocks x 256 threads, 4 cells/thread. All co-resident -> no deadlock.
// Zeroes g_cnt behind itself (restores invariant for next graph replay).
// ---------------------------------------------------------------------------
__global__ void __launch_bounds__(256) scan_kernel() {
    __shared__ int ws_incl[8];
    __shared__ int ws_excl[8];
    __shared__ int sh_prefix;

    const int tid  = threadIdx.x;
    const int bid  = blockIdx.x;
    const int lane = tid & 31;
    const int w    = tid >> 5;
    const int base = bid * 1024 + tid * 4;

    int4 v = *(const int4*)&g_cnt[base];
    int s = v.x + v.y + v.z + v.w;

    int inc = s;
#pragma unroll
    for (int o = 1; o < 32; o <<= 1) {
        int t = __shfl_up_sync(0xFFFFFFFFu, inc, o);
        if (lane >= o) inc += t;
    }
    if (lane == 31) ws_incl[w] = inc;
    __syncthreads();
    if (tid < 8) {
        int e = 0;
#pragma unroll
        for (int k = 0; k < 8; ++k)
            if (k < tid) e += ws_incl[k];
        ws_excl[tid] = e;
    }
    __syncthreads();

    const int block_total = ws_excl[7] + ws_incl[7];
    const int excl = (inc - s) + ws_excl[w];

    if (tid == 0) {
        atomicExch(&g_state[bid], (1ull << 62) | (unsigned long long)block_total);
        unsigned long long prefix = 0;
        for (int i = bid - 1; i >= 0;) {
            unsigned long long st;
            do { st = atomicAdd(&g_state[i], 0ull); } while ((st >> 62) == 0ull);
            prefix += st & 0x3FFFFFFFFFFFFFFFull;
            if ((st >> 62) == 2ull) break;
            --i;
        }
        atomicExch(&g_state[bid],
                   (2ull << 62) | (unsigned long long)(prefix + block_total));
        sh_prefix = (int)prefix;
    }
    __syncthreads();

    const int p = sh_prefix + excl;
    int4 ov = make_int4(p, p + v.x, p + v.x + v.y, p + v.x + v.y + v.z);
    *(int4*)&g_off[base]  = ov;
    *(int4*)&g_fill[base] = ov;
    *(int4*)&g_cnt[base]  = make_int4(0, 0, 0, 0);   // restore zero-invariant

    if (bid == SCANBLK - 1 && tid == 255)
        g_off[NC] = ov.w + v.w;
}

// ---------------------------------------------------------------------------
// Kernel 3: scatter means into cell-sorted order (4 means/thread, float4 loads)
// ---------------------------------------------------------------------------
__global__ void scatter_kernel(const float* __restrict__ means, int M) {
    int gid = blockIdx.x * blockDim.x + threadIdx.x;
    int m0 = gid * 4;
    if (m0 + 4 <= M) {
        const float4* p = (const float4*)means + (size_t)gid * 3;
        float4 a = p[0], b = p[1], c = p[2];
        int p0 = atomicAdd(&g_fill[cidx(a.x, a.y, a.z)], 1);
        g_pts[p0] = make_float4(a.x, a.y, a.z, 0.f);
        int p1 = atomicAdd(&g_fill[cidx(a.w, b.x, b.y)], 1);
        g_pts[p1] = make_float4(a.w, b.x, b.y, 0.f);
        int p2 = atomicAdd(&g_fill[cidx(b.z, b.w, c.x)], 1);
        g_pts[p2] = make_float4(b.z, b.w, c.x, 0.f);
        int p3 = atomicAdd(&g_fill[cidx(c.y, c.z, c.w)], 1);
        g_pts[p3] = make_float4(c.y, c.z, c.w, 0.f);
    } else if (m0 < M) {
        for (int m = m0; m < M; ++m) {
            float x = means[3*m], y = means[3*m+1], z = means[3*m+2];
            int pos = atomicAdd(&g_fill[cidx(x, y, z)], 1);
            g_pts[pos] = make_float4(x, y, z, 0.f);
        }
    }
}

// ---------------------------------------------------------------------------
// Kernel 4: warp-per-query NN with exact cell pruning + fused deterministic
// reduction (u64 fixed-point atomicAdd; last ticket writes out & resets).
//   - best starts at MARGIN: mins above MARGIN contribute 0 to the hinge.
//   - home cell first; neighbor visited only if clamp-extended box-dist^2 < best.
// ---------------------------------------------------------------------------
__global__ void __launch_bounds__(256) query_kernel(float* __restrict__ out, int Q) {
    __shared__ float wterm[8];
    const int tid  = threadIdx.x;
    const int lane = tid & 31;
    const int warp = tid >> 5;
    const int qid  = blockIdx.x * 8 + warp;

    float term = 0.f;
    if (qid < Q) {
        float4 qv = g_q[qid];
        const int cx = cell1d(qv.x), cy = cell1d(qv.y), cz = cell1d(qv.z);
        float best = MARGIN;

        // home cell first (box-dist 0)
        {
            const int home = (cz * GS + cy) * GS + cx;
            const int s0 = g_off[home], e0 = g_off[home + 1];
            float lb = best;
            for (int t = s0 + lane; t < e0; t += 32) {
                float4 m = g_pts[t];
                float dx = qv.x - m.x, dy = qv.y - m.y, dz = qv.z - m.z;
                lb = fminf(lb, fmaf(dx, dx, fmaf(dy, dy, dz * dz)));
            }
#pragma unroll
            for (int o = 16; o; o >>= 1)
                lb = fminf(lb, __shfl_xor_sync(0xFFFFFFFFu, lb, o));
            best = lb;
        }

        const int x0 = max(cx - 1, 0), x1 = min(cx + 1, GS - 1);
        const int y0 = max(cy - 1, 0), y1 = min(cy + 1, GS - 1);
        const int z0 = max(cz - 1, 0), z1 = min(cz + 1, GS - 1);

        for (int zi = z0; zi <= z1; ++zi) {
            const float az = axd(qv.z, zi);
            const float az2 = az * az;
            if (az2 >= best) continue;
            for (int yi = y0; yi <= y1; ++yi) {
                const float ay = axd(qv.y, yi);
                const float byz = fmaf(ay, ay, az2);
                if (byz >= best) continue;
                const int row = (zi * GS + yi) * GS;
                for (int xi = x0; xi <= x1; ++xi) {
                    if (xi == cx && yi == cy && zi == cz) continue;
                    const float ax = axd(qv.x, xi);
                    const float bd = fmaf(ax, ax, byz);
                    if (bd >= best) continue;
                    const int c = row + xi;
                    const int s0 = g_off[c], e0 = g_off[c + 1];
                    float lb = best;
                    for (int t = s0 + lane; t < e0; t += 32) {
                        float4 m = g_pts[t];
                        float dx = qv.x - m.x, dy = qv.y - m.y, dz = qv.z - m.z;
                        lb = fminf(lb, fmaf(dx, dx, fmaf(dy, dy, dz * dz)));
                    }
#pragma unroll
                    for (int o = 16; o; o >>= 1)
                        lb = fminf(lb, __shfl_xor_sync(0xFFFFFFFFu, lb, o));
                    best = fminf(best, lb);
                }
            }
        }
        term = MARGIN - best;            // best in [0, MARGIN]
    }

    if (lane == 0) wterm[warp] = term;
    __syncthreads();

    if (tid == 0) {
        double s = 0.0;
#pragma unroll
        for (int w = 0; w < 8; ++w) s += (double)wterm[w];
        unsigned long long fx = (unsigned long long)__double2ll_rn(s * FP_SCALE);
        atomicAdd(&g_acc, fx);
        __threadfence();
        if (atomicAdd(&g_done, 1u) == gridDim.x - 1) {
            unsigned long long tot = atomicExch(&g_acc, 0ull);
            atomicExch(&g_done, 0u);
            out[0] = (float)(((double)tot / FP_SCALE) / (double)Q);
        }
    }
}

extern "C" void kernel_launch(void* const* d_in, const int* in_sizes, int n_in,
                              void* d_out, int out_size) {
    const float* outputs = (const float*)d_in[0];  // (B, N, 3)
    const float* c2ws    = (const float*)d_in[1];  // (B, 4, 4)
    const float* scales  = (const float*)d_in[2];  // (B,)
    const float* means   = (const float*)d_in[3];  // (M, 3)

    int B = in_sizes[2];
    int Q = in_sizes[0] / 3;              // B*N
    int N = (B > 0) ? (Q / B) : 0;
    int M = in_sizes[3] / 3;
    if (Q > MAXQ) Q = MAXQ;
    if (M > MAXM) M = MAXM;

    int mthreads = (M + 3) / 4;           // 4 means per thread
    int work = mthreads > Q ? mthreads : Q;
    int nb1  = (work + 255) / 256;
    int nbs  = (mthreads + 255) / 256;
    int nqb  = (Q + 7) / 8;

    prep_count_kernel<<<nb1, 256>>>(outputs, c2ws, scales, means, N, Q, M);
    scan_kernel      <<<SCANBLK, 256>>>();
    scatter_kernel   <<<nbs, 256>>>(means, M);
    query_kernel     <<<nqb, 256>>>((float*)d_out, Q);
}